// round 15
// baseline (speedup 1.0000x reference)
#include <cuda_runtime.h>
#include <cuda_bf16.h>
#include <cuda_fp16.h>
#include <cstdint>
#include <cstddef>

// Problem constants
#define NB    32768
#define HID   512
#define KMID  264
#define DMID  384
#define DIM   256
#define MAXN  17
#define TMAX  (NB * 16)   // 524288 worst-case tokens

// ---------------- static device scratch ----------------
__device__ __align__(16) float g_keys[MAXN * HID];
__device__ __align__(16) float g_U[(size_t)NB * KMID];
__device__ int   g_n[NB];
__device__ int   g_off[NB];
__device__ int   g_total;
__device__ int   g_tok_b[TMAX];
__device__ unsigned char g_tok_k[TMAX];

// fp16 weights: (c*N + n)*72 + kl
#define B1_ELEMS (8 * DMID * 72)
#define B2_ELEMS (6 * DIM * 72)
#define B1_OFF 0
#define B2_OFF B1_ELEMS
__device__ __align__(16) __half g_Bh[B1_ELEMS + B2_ELEMS];

// fp16 A (z[b]*keys[k]), PACKED 128-row tile slabs (64 elems = 128B/row):
// ((rt*8 + c)*128 + rl)*64 + kl
__device__ __align__(16) __half g_Ah[(size_t)TMAX * 8 * 64];   // 512 MiB

__device__ __forceinline__ uint32_t smem_u32(const void* p) {
    uint32_t a;
    asm("{ .reg .u64 t; cvta.to.shared.u64 t, %1; cvt.u32.u64 %0, t; }" : "=r"(a) : "l"(p));
    return a;
}

__device__ __forceinline__ uint32_t pack_h2(float a, float b) {
    return (uint32_t)__half_as_ushort(__float2half_rn(a))
         | ((uint32_t)__half_as_ushort(__float2half_rn(b)) << 16);
}

// ---------------- weight prep: W[K,N] fp32 -> fp16, [c][n][72] ----------------
template<int BOFF>
__global__ void prep_kernel(const float* __restrict__ W, int K, int N)
{
    int t = blockIdx.x * 256 + threadIdx.x;
    int total = N * (K / 8);
    if (t >= total) return;
    int n  = t / (K / 8);
    int k0 = (t % (K / 8)) * 8;
    unsigned short hb[8];
    #pragma unroll
    for (int j = 0; j < 8; j++)
        hb[j] = __half_as_ushort(__float2half_rn(W[(size_t)(k0 + j) * N + n]));
    uint4 hv;
    hv.x = hb[0] | ((uint32_t)hb[1] << 16); hv.y = hb[2] | ((uint32_t)hb[3] << 16);
    hv.z = hb[4] | ((uint32_t)hb[5] << 16); hv.w = hb[6] | ((uint32_t)hb[7] << 16);
    int c  = k0 / 64;
    int kl = k0 % 64;
    size_t off = ((size_t)BOFF + ((size_t)c * N + n) * 72 + kl) * 2;
    *(uint4*)((char*)g_Bh + off) = hv;
}

// ---------------- keys precompute (17 rows x 8 col-chunks) ----------------
__global__ void keys_kernel(const float* __restrict__ kW1, const float* __restrict__ kb1,
                            const float* __restrict__ kg1, const float* __restrict__ kbe1,
                            const float* __restrict__ kW2, const float* __restrict__ kb2)
{
    int k = blockIdx.x;
    __shared__ float h[KMID];
    __shared__ float red[18];
    int t = threadIdx.x;   // 256
    float s = 0.f, sq = 0.f;
    for (int j = t; j < KMID; j += 256) {
        float u = kW1[k * KMID + j] + kb1[j];
        h[j] = u; s += u; sq += u * u;
    }
    for (int d = 16; d; d >>= 1) { s += __shfl_xor_sync(~0u, s, d); sq += __shfl_xor_sync(~0u, sq, d); }
    if ((t & 31) == 0) { red[t >> 5] = s; red[8 + (t >> 5)] = sq; }
    __syncthreads();
    if (t == 0) {
        float S = 0.f, SQ = 0.f;
        for (int i = 0; i < 8; i++) { S += red[i]; SQ += red[8 + i]; }
        red[16] = S; red[17] = SQ;
    }
    __syncthreads();
    float mean = red[16] * (1.f / KMID);
    float var  = red[17] * (1.f / KMID) - mean * mean;
    float inv  = rsqrtf(var + 1e-5f);
    for (int j = t; j < KMID; j += 256)
        h[j] = fmaxf((h[j] - mean) * inv * kg1[j] + kbe1[j], 0.f);
    __syncthreads();
    if (t < 64) {
        int c = blockIdx.y * 64 + t;
        float acc = kb2[c];
        #pragma unroll 4
        for (int j = 0; j < KMID; j++) acc += h[j] * kW2[(size_t)j * HID + c];
        g_keys[k * HID + c] = acc;
    }
}

// ---------------- fp32 SIMT GEMM for size-pred: 64x64 tile, high occupancy ----------------
// Per-output accumulation: ONE thread, ONE fp32 accumulator, k ascending (BK chunks
// ascending, inner k ascending) -> bit-identical to previous versions -> argmax safe.
#define BK 16
__global__ void __launch_bounds__(256)
gemm32_sp(const float* __restrict__ Ag, const float* __restrict__ Wg,
          const float* __restrict__ bias)
{
    const int N = KMID, K = HID;
    int row0 = blockIdx.y * 64;
    int col0 = blockIdx.x * 64;

    __shared__ float As[BK][64];
    __shared__ float Bs[BK][68];    // +4 pad

    int tid = threadIdx.x;
    int tr  = tid & 15;             // row group (4 rows)
    int tcg = tid >> 4;             // col group (4 cols)

    // A load mapping: row = tid>>2 (0..63), seg = tid&3 (k-offset seg*4)
    int lrow = tid >> 2, lseg = tid & 3;
    const float* arow = Ag + (size_t)(row0 + lrow) * K + lseg * 4;
    // B load mapping: br = tid>>4 (0..15), bc0 = (tid&15)*4
    int br = tid >> 4, bc0 = (tid & 15) * 4;

    float acc[4][4];
    #pragma unroll
    for (int i = 0; i < 4; i++)
        #pragma unroll
        for (int j = 0; j < 4; j++) acc[i][j] = 0.f;

    for (int k0 = 0; k0 < K; k0 += BK) {
        float4 av = *(const float4*)(arow + k0);
        As[lseg * 4 + 0][lrow] = av.x;
        As[lseg * 4 + 1][lrow] = av.y;
        As[lseg * 4 + 2][lrow] = av.z;
        As[lseg * 4 + 3][lrow] = av.w;
        #pragma unroll
        for (int j = 0; j < 4; j++) {
            int col = col0 + bc0 + j;
            Bs[br][bc0 + j] = (col < N) ? Wg[(size_t)(k0 + br) * N + col] : 0.f;
        }
        __syncthreads();
        #pragma unroll
        for (int k = 0; k < BK; k++) {
            float a[4], b[4];
            #pragma unroll
            for (int i = 0; i < 4; i++) a[i] = As[k][tr * 4 + i];
            #pragma unroll
            for (int j = 0; j < 4; j++) b[j] = Bs[k][tcg * 4 + j];
            #pragma unroll
            for (int i = 0; i < 4; i++)
                #pragma unroll
                for (int j = 0; j < 4; j++)
                    acc[i][j] = fmaf(a[i], b[j], acc[i][j]);
        }
        __syncthreads();
    }
    #pragma unroll
    for (int i = 0; i < 4; i++) {
        int row = row0 + tr * 4 + i;
        #pragma unroll
        for (int j = 0; j < 4; j++) {
            int col = col0 + tcg * 4 + j;
            if (col < N) g_U[(size_t)row * N + col] = acc[i][j] + bias[col];
        }
    }
}

// ---------------- size-pred: LN + relu + @sp_W2 + argmax ----------------
__global__ void __launch_bounds__(256)
sizepred_kernel(const float* __restrict__ W2, const float* __restrict__ b2,
                const float* __restrict__ g1, const float* __restrict__ be1)
{
    __shared__ float sW2[KMID * MAXN];
    int tid = threadIdx.x;
    for (int i = tid; i < KMID * MAXN; i += 256) sW2[i] = W2[i];
    __syncthreads();

    int w = blockIdx.x * 8 + (tid >> 5);
    int lane = tid & 31;
    if (w >= NB) return;
    const float* u = g_U + (size_t)w * KMID;
    float vals[9];
    float s = 0.f, sq = 0.f;
    #pragma unroll
    for (int i = 0; i < 9; i++) {
        int j = lane + 32 * i;
        float v = (j < KMID) ? u[j] : 0.f;
        vals[i] = v; s += v; sq += v * v;
    }
    for (int d = 16; d; d >>= 1) { s += __shfl_xor_sync(~0u, s, d); sq += __shfl_xor_sync(~0u, sq, d); }
    float mean = s * (1.f / KMID);
    float var  = sq * (1.f / KMID) - mean * mean;
    float inv  = rsqrtf(var + 1e-5f);
    float logit[MAXN];
    #pragma unroll
    for (int o = 0; o < MAXN; o++) logit[o] = 0.f;
    #pragma unroll
    for (int i = 0; i < 9; i++) {
        int j = lane + 32 * i;
        if (j < KMID) {
            float h = fmaxf((vals[i] - mean) * inv * g1[j] + be1[j], 0.f);
            #pragma unroll
            for (int o = 0; o < MAXN; o++) logit[o] += h * sW2[j * MAXN + o];
        }
    }
    #pragma unroll
    for (int o = 0; o < MAXN; o++)
        for (int d = 16; d; d >>= 1) logit[o] += __shfl_xor_sync(~0u, logit[o], d);
    if (lane == 0) {
        float best = -1e30f; int bi = 0;
        #pragma unroll
        for (int o = 0; o < MAXN; o++) {
            float v = logit[o] + b2[o];
            if (v > best) { best = v; bi = o; }
        }
        g_n[w] = bi;
    }
}

// ---------------- exclusive scan ----------------
__global__ void scan_kernel()
{
    __shared__ int warpsum[32];
    int t = threadIdx.x, l = t & 31, w = t >> 5;
    int base = t * 32;
    int loc[32];
    int s = 0;
    #pragma unroll
    for (int i = 0; i < 32; i++) { loc[i] = s; s += g_n[base + i]; }
    int inc = s;
    #pragma unroll
    for (int d = 1; d < 32; d <<= 1) { int v = __shfl_up_sync(~0u, inc, d); if (l >= d) inc += v; }
    if (l == 31) warpsum[w] = inc;
    __syncthreads();
    if (w == 0) {
        int v = warpsum[l];
        #pragma unroll
        for (int d = 1; d < 32; d <<= 1) { int u2 = __shfl_up_sync(~0u, v, d); if (l >= d) v += u2; }
        warpsum[l] = v;
    }
    __syncthreads();
    int wbase = (w > 0) ? warpsum[w - 1] : 0;
    int exc = wbase + inc - s;
    #pragma unroll
    for (int i = 0; i < 32; i++) g_off[base + i] = exc + loc[i];
    if (t == 1023) g_total = wbase + inc;
}

__global__ void tokmap_kernel()
{
    int b = blockIdx.x * 256 + threadIdx.x;
    if (b >= NB) return;
    int off = g_off[b], n = g_n[b];
    for (int j = 0; j < n; j++) { g_tok_b[off + j] = b; g_tok_k[off + j] = (unsigned char)j; }
}

// ---------------- gatherA: zp = z[b]*keys[k] -> fp16, PACKED 128-row slabs ----------------
__global__ void gatherA_kernel(const float* __restrict__ z)
{
    int idx = blockIdx.x * 256 + threadIdx.x;
    int T = g_total;
    int rp = (T + 127) & ~127;
    if (idx >= rp * 4) return;
    int row = idx >> 2, q = idx & 3;
    int rc = min(row, T - 1);
    int b  = g_tok_b[rc];
    int kk = g_tok_k[rc];
    const float* zr = z + (size_t)b * HID;
    const float* kr = g_keys + kk * HID;
    int rt = row >> 7, rl = row & 127;
    #pragma unroll
    for (int jj = 0; jj < 16; jj++) {
        int kg = q * 128 + jj * 8;
        float4 a0 = *(const float4*)(zr + kg),     a1 = *(const float4*)(zr + kg + 4);
        float4 k0 = *(const float4*)(kr + kg),     k1 = *(const float4*)(kr + kg + 4);
        uint4 hv;
        hv.x = pack_h2(a0.x * k0.x, a0.y * k0.y);
        hv.y = pack_h2(a0.z * k0.z, a0.w * k0.w);
        hv.z = pack_h2(a1.x * k1.x, a1.y * k1.y);
        hv.w = pack_h2(a1.z * k1.z, a1.w * k1.w);
        int c = kg >> 6, kl = kg & 63;
        size_t off = (((size_t)(rt * 8 + c) * 128 + rl) * 64 + kl) * 2;
        *(uint4*)((char*)g_Ah + off) = hv;
    }
}

// ---------------- FUSED decoder: out = relu(A@W1+b1)@W2+b2, one CTA per 128-row tile ----------------
// Phase 1: 3 n-tiles of dec1 (A slabs via cp.async, 3-stage pipeline), H fp16 -> SMEM slab.
// Phase 2: 2 n-tiles of dec2; ALL 6 B chunks preloaded -> barrier-free mainloop; A from Hbuf.
// smem: Hbuf 110592 | pipe 110592. Total 221184.
// Scratch arrays referenced DEVICE-SIDE only (ATS zero-shadow bug, rounds 4/5/6).
__global__ void __launch_bounds__(256, 1)
hmma_fused(const float* __restrict__ b1, const float* __restrict__ b2, float* __restrict__ Cg)
{
    constexpr int NC1 = HID / 64;   // 8
    constexpr int NC2 = DMID / 64;  // 6
    constexpr int CB  = 128 * 144;
    constexpr int CBG = 128 * 128;
    constexpr int HB  = 6 * CB;     // 110592
    constexpr int STG = 2 * CB;     // 36864 (phase-1: A at 0, B at CB)

    int Meff = g_total;
    int row0 = blockIdx.x * 128;
    if (row0 >= Meff) return;
    int rt = blockIdx.x;

    extern __shared__ char dyn[];
    const uint32_t dynb = smem_u32(dyn);
    const uint32_t hbuf = dynb;
    const uint32_t pipe = dynb + HB;

    int tid  = threadIdx.x;
    int wid  = tid >> 5;
    int lane = tid & 31;
    int warp_m = wid & 3;
    int warp_n = wid >> 2;

    uint32_t a_off = (uint32_t)(warp_m * 32 + (lane & 15)) * 144 + ((lane >> 4) << 3) * 2;
    uint32_t b_off = (uint32_t)(warp_n * 64 + (lane & 7) + ((lane >> 4) << 3)) * 144
                   + (((lane >> 3) & 1) << 3) * 2;

    int rl_base = warp_m * 32 + (lane >> 2);
    int cl_base = warp_n * 64 + (lane & 3) * 2;

    const char* Ahg = (const char*)g_Ah;
    const char* B1g = (const char*)g_Bh;
    const char* B2g = (const char*)g_Bh + (size_t)B2_OFF * 2;

    auto cpA = [&](int c, int st) {
        uint32_t dh = pipe + st * STG;
        const char* sh = Ahg + (size_t)(rt * NC1 + c) * CBG;
        #pragma unroll
        for (int it = 0; it < 4; it++) {
            int tt = tid + 256 * it;
            int row = tt >> 3, sg = tt & 7;
            asm volatile("cp.async.cg.shared.global [%0], [%1], 16;"
                :: "r"(dh + row * 144 + sg * 16), "l"(sh + row * 128 + sg * 16));
        }
    };
    auto cpBto = [&](uint32_t dh, const char* Bg, int NT, int n0, int c) {
        const char* sh = Bg + ((size_t)c * NT + n0) * 144;
        #pragma unroll
        for (int it = 0; it < 5; it++) {
            int tt = tid + 256 * it;
            if (tt < 128 * 9) {
                int row = tt / 9, sg = tt - row * 9;
                uint32_t o = row * 144 + sg * 16;
                asm volatile("cp.async.cg.shared.global [%0], [%1], 16;" :: "r"(dh + o), "l"(sh + o));
            }
        }
    };

    float acc[2][8][4];

    // ================= Phase 1: dec1, 3 n-tiles =================
    for (int nt = 0; nt < 3; nt++) {
        int n0 = nt * 128;
        #pragma unroll
        for (int mi = 0; mi < 2; mi++)
            #pragma unroll
            for (int fj = 0; fj < 8; fj++)
                #pragma unroll
                for (int q = 0; q < 4; q++) acc[mi][fj][q] = 0.f;

        cpA(0, 0); cpBto(pipe + 0 * STG + CB, B1g, DMID, n0, 0);
        asm volatile("cp.async.commit_group;");
        cpA(1, 1); cpBto(pipe + 1 * STG + CB, B1g, DMID, n0, 1);
        asm volatile("cp.async.commit_group;");
        asm volatile("cp.async.wait_group 1;");
        __syncthreads();

        for (int c = 0; c < NC1; c++) {
            int st = c % 3;
            if (c + 2 < NC1) {
                int st2 = (c + 2) % 3;
                cpA(c + 2, st2); cpBto(pipe + st2 * STG + CB, B1g, DMID, n0, c + 2);
                asm volatile("cp.async.commit_group;");
            }
            uint32_t Ab = pipe + st * STG + a_off;
            uint32_t Bb = pipe + st * STG + CB + b_off;
            #pragma unroll
            for (int k16 = 0; k16 < 4; k16++) {
                uint32_t kb = (uint32_t)k16 * 32;
                uint32_t af[2][4];
                #pragma unroll
                for (int mi = 0; mi < 2; mi++) {
                    asm volatile("ldmatrix.sync.aligned.m8n8.x4.shared.b16 {%0,%1,%2,%3}, [%4];"
                        : "=r"(af[mi][0]), "=r"(af[mi][1]), "=r"(af[mi][2]), "=r"(af[mi][3])
                        : "r"(Ab + mi * 2304 + kb));
                }
                uint32_t bf[4][4];
                #pragma unroll
                for (int gj = 0; gj < 4; gj++) {
                    asm volatile("ldmatrix.sync.aligned.m8n8.x4.shared.b16 {%0,%1,%2,%3}, [%4];"
                        : "=r"(bf[gj][0]), "=r"(bf[gj][1]), "=r"(bf[gj][2]), "=r"(bf[gj][3])
                        : "r"(Bb + gj * 2304 + kb));
                }
                #pragma unroll
                for (int mi = 0; mi < 2; mi++)
                    #pragma unroll
                    for (int gj = 0; gj < 4; gj++)
                        #pragma unroll
                        for (int h = 0; h < 2; h++) {
                            int fj = gj * 2 + h;
                            asm volatile(
                                "mma.sync.aligned.m16n8k16.row.col.f32.f16.f16.f32 "
                                "{%0,%1,%2,%3},{%4,%5,%6,%7},{%8,%9},{%0,%1,%2,%3};"
                                : "+f"(acc[mi][fj][0]), "+f"(acc[mi][fj][1]),
                                  "+f"(acc[mi][fj][2]), "+f"(acc[mi][fj][3])
                                : "r"(af[mi][0]), "r"(af[mi][1]), "r"(af[mi][2]), "r"(af[mi][3]),
                                  "r"(bf[gj][h * 2]), "r"(bf[gj][h * 2 + 1]));
                        }
            }
            if (c + 1 < NC1) {
                if (c + 2 < NC1) { asm volatile("cp.async.wait_group 1;"); }
                else             { asm volatile("cp.async.wait_group 0;"); }
                __syncthreads();
            }
        }

        // epilogue: relu + bias -> fp16 into SMEM Hbuf (slab layout)
        #pragma unroll
        for (int mi = 0; mi < 2; mi++) {
            #pragma unroll
            for (int fj = 0; fj < 8; fj++) {
                int colg = n0 + cl_base + fj * 8;
                int hc = colg >> 6, kl = colg & 63;
                float2 bv = *(const float2*)(b1 + colg);
                #pragma unroll
                for (int h2 = 0; h2 < 2; h2++) {
                    int row_l = rl_base + mi * 16 + h2 * 8;
                    float v0 = fmaxf(acc[mi][fj][h2 * 2 + 0] + bv.x, 0.f);
                    float v1 = fmaxf(acc[mi][fj][h2 * 2 + 1] + bv.y, 0.f);
                    *(uint32_t*)(dyn + (hc * 128 + row_l) * 144 + kl * 2) = pack_h2(v0, v1);
                }
            }
        }
        __syncthreads();
    }

    // ================= Phase 2: dec2, 2 n-tiles, A from SMEM H, barrier-free mainloop =================
    for (int nt2 = 0; nt2 < 2; nt2++) {
        int n0 = nt2 * 128;
        if (nt2 == 1) __syncthreads();
        #pragma unroll
        for (int mi = 0; mi < 2; mi++)
            #pragma unroll
            for (int fj = 0; fj < 8; fj++)
                #pragma unroll
                for (int q = 0; q < 4; q++) acc[mi][fj][q] = 0.f;

        #pragma unroll
        for (int c = 0; c < NC2; c++)
            cpBto(pipe + c * CB, B2g, DIM, n0, c);
        asm volatile("cp.async.commit_group;");
        asm volatile("cp.async.wait_group 0;");
        __syncthreads();

        for (int c = 0; c < NC2; c++) {
            uint32_t Ab = hbuf + c * CB + a_off;
            uint32_t Bb = pipe + c * CB + b_off;
            #pragma unroll
            for (int k16 = 0; k16 < 4; k16++) {
                uint32_t kb = (uint32_t)k16 * 32;
                uint32_t af[2][4];
                #pragma unroll
                for (int mi = 0; mi < 2; mi++) {
                    asm volatile("ldmatrix.sync.aligned.m8n8.x4.shared.b16 {%0,%1,%2,%3}, [%4];"
                        : "=r"(af[mi][0]), "=r"(af[mi][1]), "=r"(af[mi][2]), "=r"(af[mi][3])
                        : "r"(Ab + mi * 2304 + kb));
                }
                uint32_t bf[4][4];
                #pragma unroll
                for (int gj = 0; gj < 4; gj++) {
                    asm volatile("ldmatrix.sync.aligned.m8n8.x4.shared.b16 {%0,%1,%2,%3}, [%4];"
                        : "=r"(bf[gj][0]), "=r"(bf[gj][1]), "=r"(bf[gj][2]), "=r"(bf[gj][3])
                        : "r"(Bb + gj * 2304 + kb));
                }
                #pragma unroll
                for (int mi = 0; mi < 2; mi++)
                    #pragma unroll
                    for (int gj = 0; gj < 4; gj++)
                        #pragma unroll
                        for (int h = 0; h < 2; h++) {
                            int fj = gj * 2 + h;
                            asm volatile(
                                "mma.sync.aligned.m16n8k16.row.col.f32.f16.f16.f32 "
                                "{%0,%1,%2,%3},{%4,%5,%6,%7},{%8,%9},{%0,%1,%2,%3};"
                                : "+f"(acc[mi][fj][0]), "+f"(acc[mi][fj][1]),
                                  "+f"(acc[mi][fj][2]), "+f"(acc[mi][fj][3])
                                : "r"(af[mi][0]), "r"(af[mi][1]), "r"(af[mi][2]), "r"(af[mi][3]),
                                  "r"(bf[gj][h * 2]), "r"(bf[gj][h * 2 + 1]));
                        }
            }
        }

        // epilogue: bias -> fp32 out
        #pragma unroll
        for (int mi = 0; mi < 2; mi++) {
            int r0 = row0 + rl_base + mi * 16;
            #pragma unroll
            for (int fj = 0; fj < 8; fj++) {
                int col = n0 + cl_base + fj * 8;
                float2 bv = *(const float2*)(b2 + col);
                float v0 = acc[mi][fj][0] + bv.x;
                float v1 = acc[mi][fj][1] + bv.y;
                float v2 = acc[mi][fj][2] + bv.x;
                float v3 = acc[mi][fj][3] + bv.y;
                if (r0 < Meff)     *(float2*)(Cg + (size_t)r0 * DIM + col)       = make_float2(v0, v1);
                if (r0 + 8 < Meff) *(float2*)(Cg + (size_t)(r0 + 8) * DIM + col) = make_float2(v2, v3);
            }
        }
    }
}

__global__ void batchout_kernel(float* __restrict__ out, long long out_size)
{
    int t = blockIdx.x * 256 + threadIdx.x;
    int total = g_total;
    if ((long long)total * 257 > out_size) return;
    if (t < total) out[(long long)total * 256 + t] = (float)g_tok_b[t];
}

// ---------------- launch ----------------
extern "C" void kernel_launch(void* const* d_in, const int* in_sizes, int n_in,
                              void* d_out, int out_size)
{
    const float* z     = (const float*)d_in[0];
    const float* kW1   = (const float*)d_in[1];
    const float* kb1   = (const float*)d_in[2];
    const float* kg1   = (const float*)d_in[3];
    const float* kbe1  = (const float*)d_in[4];
    const float* kW2   = (const float*)d_in[5];
    const float* kb2   = (const float*)d_in[6];
    const float* dW1   = (const float*)d_in[7];
    const float* db1   = (const float*)d_in[8];
    const float* dW2   = (const float*)d_in[9];
    const float* db2   = (const float*)d_in[10];
    const float* spW1  = (const float*)d_in[11];
    const float* spb1  = (const float*)d_in[12];
    const float* spg1  = (const float*)d_in[13];
    const float* spbe1 = (const float*)d_in[14];
    const float* spW2  = (const float*)d_in[15];
    const float* spb2  = (const float*)d_in[16];
    float* out = (float*)d_out;

    constexpr int SMEM_FUSED = 6 * 128 * 144 + 3 * 2 * 128 * 144;   // 221184
    cudaFuncSetAttribute(hmma_fused, cudaFuncAttributeMaxDynamicSharedMemorySize, SMEM_FUSED);

    // weight prep (fp16)
    prep_kernel<B1_OFF><<<(DMID * (HID / 8) + 255) / 256, 256>>>(dW1, HID, DMID);
    prep_kernel<B2_OFF><<<(DIM * (DMID / 8) + 255) / 256, 256>>>(dW2, DMID, DIM);

    // 17 key rows
    keys_kernel<<<dim3(17, 8), 256>>>(kW1, kb1, kg1, kbe1, kW2, kb2);

    // sp GEMM (fp32 scalar FFMA, 64x64 tiles for occupancy; bit-identical accumulation)
    gemm32_sp<<<dim3((KMID + 63) / 64, NB / 64), 256>>>(z, spW1, spb1);

    // size-pred -> g_n -> offsets -> token map
    sizepred_kernel<<<NB / 8, 256>>>(spW2, spb2, spg1, spbe1);
    scan_kernel<<<1, 1024>>>();
    tokmap_kernel<<<NB / 256, 256>>>();

    // pre-round A = z[b]*keys[k] (fp16)
    gatherA_kernel<<<TMAX * 4 / 256, 256>>>(z);

    // fused decoder: both layers, one CTA per 128-row tile
    hmma_fused<<<TMAX / 128, 256, SMEM_FUSED>>>(db1, db2, out);

    // optional batch ids
    batchout_kernel<<<TMAX / 256, 256>>>(out, (long long)out_size);
}

// round 16
// speedup vs baseline: 1.0798x; 1.0798x over previous
#include <cuda_runtime.h>
#include <cuda_bf16.h>
#include <cuda_fp16.h>
#include <cstdint>
#include <cstddef>

// Problem constants
#define NB    32768
#define HID   512
#define KMID  264
#define DMID  384
#define DIM   256
#define MAXN  17
#define TMAX  (NB * 16)   // 524288 worst-case tokens
#define NSPPAD 384        // sp GEMM N padded to 3 n-tiles
#define TAU   0.02f       // argmax margin gate (~100 sigma of fp16-path logit noise)

// ---------------- static device scratch ----------------
__device__ __align__(16) float g_keys[MAXN * HID];
__device__ __align__(16) float g_U[(size_t)NB * KMID];
__device__ int   g_n[NB];
__device__ int   g_off[NB];
__device__ int   g_total;
__device__ int   g_tok_b[TMAX];
__device__ unsigned char g_tok_k[TMAX];
__device__ int   g_flag[NB];
__device__ int   g_nflag;

// fp16 weights: (c*N + n)*72 + kl
#define B1_ELEMS (8 * DMID * 72)
#define B2_ELEMS (6 * DIM * 72)
#define B1_OFF 0
#define B2_OFF B1_ELEMS
__device__ __align__(16) __half g_Bh[B1_ELEMS + B2_ELEMS];
__device__ __align__(16) __half g_Bsp[8 * NSPPAD * 72];        // spW1 fp16, padded

// fp16 A (z[b]*keys[k]), PACKED 128-row tile slabs; and z itself in the same slab form
__device__ __align__(16) __half g_Ah[(size_t)TMAX * 8 * 64];   // 512 MiB
__device__ __align__(16) __half g_Az[(size_t)NB * 8 * 64];     // 33.5 MiB (z slabs)

__device__ __forceinline__ uint32_t smem_u32(const void* p) {
    uint32_t a;
    asm("{ .reg .u64 t; cvta.to.shared.u64 t, %1; cvt.u32.u64 %0, t; }" : "=r"(a) : "l"(p));
    return a;
}

__device__ __forceinline__ uint32_t pack_h2(float a, float b) {
    return (uint32_t)__half_as_ushort(__float2half_rn(a))
         | ((uint32_t)__half_as_ushort(__float2half_rn(b)) << 16);
}

// ---------------- weight prep: W[K,N] fp32 -> fp16, [c][n][72] ----------------
template<int BOFF>
__global__ void prep_kernel(const float* __restrict__ W, int K, int N)
{
    int t = blockIdx.x * 256 + threadIdx.x;
    int total = N * (K / 8);
    if (t >= total) return;
    int n  = t / (K / 8);
    int k0 = (t % (K / 8)) * 8;
    unsigned short hb[8];
    #pragma unroll
    for (int j = 0; j < 8; j++)
        hb[j] = __half_as_ushort(__float2half_rn(W[(size_t)(k0 + j) * N + n]));
    uint4 hv;
    hv.x = hb[0] | ((uint32_t)hb[1] << 16); hv.y = hb[2] | ((uint32_t)hb[3] << 16);
    hv.z = hb[4] | ((uint32_t)hb[5] << 16); hv.w = hb[6] | ((uint32_t)hb[7] << 16);
    int c  = k0 / 64;
    int kl = k0 % 64;
    size_t off = ((size_t)BOFF + ((size_t)c * N + n) * 72 + kl) * 2;
    *(uint4*)((char*)g_Bh + off) = hv;
}

// spW1 [512][264] -> fp16 [c][n(384 padded)][72], zero-fill n >= 264
__global__ void prep_sp_kernel(const float* __restrict__ W)
{
    int t = blockIdx.x * 256 + threadIdx.x;
    int total = NSPPAD * (HID / 8);
    if (t >= total) return;
    int n  = t / (HID / 8);
    int k0 = (t % (HID / 8)) * 8;
    unsigned short hb[8];
    #pragma unroll
    for (int j = 0; j < 8; j++) {
        float v = (n < KMID) ? W[(size_t)(k0 + j) * KMID + n] : 0.f;
        hb[j] = __half_as_ushort(__float2half_rn(v));
    }
    uint4 hv;
    hv.x = hb[0] | ((uint32_t)hb[1] << 16); hv.y = hb[2] | ((uint32_t)hb[3] << 16);
    hv.z = hb[4] | ((uint32_t)hb[5] << 16); hv.w = hb[6] | ((uint32_t)hb[7] << 16);
    int c = k0 / 64, kl = k0 % 64;
    *(uint4*)((char*)g_Bsp + (((size_t)c * NSPPAD + n) * 72 + kl) * 2) = hv;
}

// z [NB][512] fp32 -> fp16 slabs [rt][c][128][64]; also resets flag counter
__global__ void zprep_kernel(const float* __restrict__ z)
{
    int idx = blockIdx.x * 256 + threadIdx.x;
    if (idx == 0) g_nflag = 0;
    if (idx >= NB * 4) return;
    int row = idx >> 2, q = idx & 3;
    int rt = row >> 7, rl = row & 127;
    const float* zr = z + (size_t)row * HID;
    #pragma unroll
    for (int jj = 0; jj < 16; jj++) {
        int kg = q * 128 + jj * 8;
        float4 a0 = *(const float4*)(zr + kg), a1 = *(const float4*)(zr + kg + 4);
        uint4 hv;
        hv.x = pack_h2(a0.x, a0.y); hv.y = pack_h2(a0.z, a0.w);
        hv.z = pack_h2(a1.x, a1.y); hv.w = pack_h2(a1.z, a1.w);
        int c = kg >> 6, kl = kg & 63;
        *(uint4*)((char*)g_Az + (((size_t)(rt * 8 + c) * 128 + rl) * 64 + kl) * 2) = hv;
    }
}

// ---------------- keys precompute (17 rows x 8 col-chunks) ----------------
__global__ void keys_kernel(const float* __restrict__ kW1, const float* __restrict__ kb1,
                            const float* __restrict__ kg1, const float* __restrict__ kbe1,
                            const float* __restrict__ kW2, const float* __restrict__ kb2)
{
    int k = blockIdx.x;
    __shared__ float h[KMID];
    __shared__ float red[18];
    int t = threadIdx.x;
    float s = 0.f, sq = 0.f;
    for (int j = t; j < KMID; j += 256) {
        float u = kW1[k * KMID + j] + kb1[j];
        h[j] = u; s += u; sq += u * u;
    }
    for (int d = 16; d; d >>= 1) { s += __shfl_xor_sync(~0u, s, d); sq += __shfl_xor_sync(~0u, sq, d); }
    if ((t & 31) == 0) { red[t >> 5] = s; red[8 + (t >> 5)] = sq; }
    __syncthreads();
    if (t == 0) {
        float S = 0.f, SQ = 0.f;
        for (int i = 0; i < 8; i++) { S += red[i]; SQ += red[8 + i]; }
        red[16] = S; red[17] = SQ;
    }
    __syncthreads();
    float mean = red[16] * (1.f / KMID);
    float var  = red[17] * (1.f / KMID) - mean * mean;
    float inv  = rsqrtf(var + 1e-5f);
    for (int j = t; j < KMID; j += 256)
        h[j] = fmaxf((h[j] - mean) * inv * kg1[j] + kbe1[j], 0.f);
    __syncthreads();
    if (t < 64) {
        int c = blockIdx.y * 64 + t;
        float acc = kb2[c];
        #pragma unroll 4
        for (int j = 0; j < KMID; j++) acc += h[j] * kW2[(size_t)j * HID + c];
        g_keys[k * HID + c] = acc;
    }
}

// ---------------- sp GEMM on HMMA: U = fp16(z) @ fp16(spW1) + b, fp32 out ----------------
__global__ void __launch_bounds__(256, 1)
sp_hmma(const float* __restrict__ bias)
{
    constexpr int NC = HID / 64;    // 8
    constexpr int CB  = 128 * 144;
    constexpr int CBG = 128 * 128;
    constexpr int STG = 2 * CB;

    int rt = blockIdx.y;
    int row0 = rt * 128;
    int n0 = blockIdx.x * 128;

    extern __shared__ char dyn[];
    const uint32_t dynb = smem_u32(dyn);
    int tid  = threadIdx.x;
    int wid  = tid >> 5;
    int lane = tid & 31;
    int warp_m = wid & 3;
    int warp_n = wid >> 2;

    uint32_t a_off = (uint32_t)(warp_m * 32 + (lane & 15)) * 144 + ((lane >> 4) << 3) * 2;
    uint32_t b_off = (uint32_t)(warp_n * 64 + (lane & 7) + ((lane >> 4) << 3)) * 144
                   + (((lane >> 3) & 1) << 3) * 2;
    int rl_base = warp_m * 32 + (lane >> 2);
    int cl_base = warp_n * 64 + (lane & 3) * 2;

    auto cpA = [&](int c, int st) {
        uint32_t dh = dynb + st * STG;
        const char* sh = (const char*)g_Az + (size_t)(rt * NC + c) * CBG;
        #pragma unroll
        for (int it = 0; it < 4; it++) {
            int tt = tid + 256 * it;
            int row = tt >> 3, sg = tt & 7;
            asm volatile("cp.async.cg.shared.global [%0], [%1], 16;"
                :: "r"(dh + row * 144 + sg * 16), "l"(sh + row * 128 + sg * 16));
        }
    };
    auto cpB = [&](int c, int st) {
        uint32_t dh = dynb + st * STG + CB;
        const char* sh = (const char*)g_Bsp + ((size_t)c * NSPPAD + n0) * 144;
        #pragma unroll
        for (int it = 0; it < 5; it++) {
            int tt = tid + 256 * it;
            if (tt < 128 * 9) {
                int row = tt / 9, sg = tt - row * 9;
                uint32_t o = row * 144 + sg * 16;
                asm volatile("cp.async.cg.shared.global [%0], [%1], 16;" :: "r"(dh + o), "l"(sh + o));
            }
        }
    };

    float acc[2][8][4];
    #pragma unroll
    for (int mi = 0; mi < 2; mi++)
        #pragma unroll
        for (int fj = 0; fj < 8; fj++)
            #pragma unroll
            for (int q = 0; q < 4; q++) acc[mi][fj][q] = 0.f;

    cpA(0, 0); cpB(0, 0);
    asm volatile("cp.async.commit_group;");
    cpA(1, 1); cpB(1, 1);
    asm volatile("cp.async.commit_group;");
    asm volatile("cp.async.wait_group 1;");
    __syncthreads();

    for (int c = 0; c < NC; c++) {
        int st = c % 3;
        if (c + 2 < NC) {
            int st2 = (c + 2) % 3;
            cpA(c + 2, st2); cpB(c + 2, st2);
            asm volatile("cp.async.commit_group;");
        }
        uint32_t Ab = dynb + st * STG + a_off;
        uint32_t Bb = dynb + st * STG + CB + b_off;
        #pragma unroll
        for (int k16 = 0; k16 < 4; k16++) {
            uint32_t kb = (uint32_t)k16 * 32;
            uint32_t af[2][4];
            #pragma unroll
            for (int mi = 0; mi < 2; mi++) {
                asm volatile("ldmatrix.sync.aligned.m8n8.x4.shared.b16 {%0,%1,%2,%3}, [%4];"
                    : "=r"(af[mi][0]), "=r"(af[mi][1]), "=r"(af[mi][2]), "=r"(af[mi][3])
                    : "r"(Ab + mi * 2304 + kb));
            }
            uint32_t bf[4][4];
            #pragma unroll
            for (int gj = 0; gj < 4; gj++) {
                asm volatile("ldmatrix.sync.aligned.m8n8.x4.shared.b16 {%0,%1,%2,%3}, [%4];"
                    : "=r"(bf[gj][0]), "=r"(bf[gj][1]), "=r"(bf[gj][2]), "=r"(bf[gj][3])
                    : "r"(Bb + gj * 2304 + kb));
            }
            #pragma unroll
            for (int mi = 0; mi < 2; mi++)
                #pragma unroll
                for (int gj = 0; gj < 4; gj++)
                    #pragma unroll
                    for (int h = 0; h < 2; h++) {
                        int fj = gj * 2 + h;
                        asm volatile(
                            "mma.sync.aligned.m16n8k16.row.col.f32.f16.f16.f32 "
                            "{%0,%1,%2,%3},{%4,%5,%6,%7},{%8,%9},{%0,%1,%2,%3};"
                            : "+f"(acc[mi][fj][0]), "+f"(acc[mi][fj][1]),
                              "+f"(acc[mi][fj][2]), "+f"(acc[mi][fj][3])
                            : "r"(af[mi][0]), "r"(af[mi][1]), "r"(af[mi][2]), "r"(af[mi][3]),
                              "r"(bf[gj][h * 2]), "r"(bf[gj][h * 2 + 1]));
                    }
        }
        if (c + 1 < NC) {
            if (c + 2 < NC) { asm volatile("cp.async.wait_group 1;"); }
            else            { asm volatile("cp.async.wait_group 0;"); }
            __syncthreads();
        }
    }

    #pragma unroll
    for (int mi = 0; mi < 2; mi++) {
        int r0 = row0 + rl_base + mi * 16;
        #pragma unroll
        for (int fj = 0; fj < 8; fj++) {
            int col = n0 + cl_base + fj * 8;
            if (col + 1 < KMID) {
                float2 bv = *(const float2*)(bias + col);
                *(float2*)(g_U + (size_t)r0 * KMID + col) =
                    make_float2(acc[mi][fj][0] + bv.x, acc[mi][fj][1] + bv.y);
                *(float2*)(g_U + (size_t)(r0 + 8) * KMID + col) =
                    make_float2(acc[mi][fj][2] + bv.x, acc[mi][fj][3] + bv.y);
            }
        }
    }
}

// ---------------- size-pred: LN + relu + @sp_W2 + argmax + margin flag ----------------
__global__ void __launch_bounds__(256)
sizepred_kernel(const float* __restrict__ W2, const float* __restrict__ b2,
                const float* __restrict__ g1, const float* __restrict__ be1)
{
    __shared__ float sW2[KMID * MAXN];
    int tid = threadIdx.x;
    for (int i = tid; i < KMID * MAXN; i += 256) sW2[i] = W2[i];
    __syncthreads();

    int w = blockIdx.x * 8 + (tid >> 5);
    int lane = tid & 31;
    if (w >= NB) return;
    const float* u = g_U + (size_t)w * KMID;
    float vals[9];
    float s = 0.f, sq = 0.f;
    #pragma unroll
    for (int i = 0; i < 9; i++) {
        int j = lane + 32 * i;
        float v = (j < KMID) ? u[j] : 0.f;
        vals[i] = v; s += v; sq += v * v;
    }
    for (int d = 16; d; d >>= 1) { s += __shfl_xor_sync(~0u, s, d); sq += __shfl_xor_sync(~0u, sq, d); }
    float mean = s * (1.f / KMID);
    float var  = sq * (1.f / KMID) - mean * mean;
    float inv  = rsqrtf(var + 1e-5f);
    float logit[MAXN];
    #pragma unroll
    for (int o = 0; o < MAXN; o++) logit[o] = 0.f;
    #pragma unroll
    for (int i = 0; i < 9; i++) {
        int j = lane + 32 * i;
        if (j < KMID) {
            float h = fmaxf((vals[i] - mean) * inv * g1[j] + be1[j], 0.f);
            #pragma unroll
            for (int o = 0; o < MAXN; o++) logit[o] += h * sW2[j * MAXN + o];
        }
    }
    #pragma unroll
    for (int o = 0; o < MAXN; o++)
        for (int d = 16; d; d >>= 1) logit[o] += __shfl_xor_sync(~0u, logit[o], d);
    if (lane == 0) {
        float best = -1e30f, second = -1e30f; int bi = 0;
        #pragma unroll
        for (int o = 0; o < MAXN; o++) {
            float v = logit[o] + b2[o];
            if (v > best) { second = best; best = v; bi = o; }
            else if (v > second) second = v;
        }
        g_n[w] = bi;
        if (best - second < TAU) {
            int p = atomicAdd(&g_nflag, 1);
            if (p < NB) g_flag[p] = w;
        }
    }
}

// ---------------- fp32 exact fallback for margin-flagged rows ----------------
__global__ void __launch_bounds__(256)
sp_fallback(const float* __restrict__ z,
            const float* __restrict__ W1, const float* __restrict__ b1,
            const float* __restrict__ g1, const float* __restrict__ be1,
            const float* __restrict__ W2, const float* __restrict__ b2)
{
    __shared__ float u[KMID];
    __shared__ float h[KMID];
    __shared__ float red[18];
    __shared__ float lg[MAXN];
    int tid = threadIdx.x;
    int nf = g_nflag;
    if (nf > NB) nf = NB;
    for (int f = blockIdx.x; f < nf; f += gridDim.x) {
        int w = g_flag[f];
        const float* zr = z + (size_t)w * HID;
        for (int j = tid; j < KMID; j += 256) {
            float acc = b1[j];
            #pragma unroll 4
            for (int k = 0; k < HID; k++) acc += zr[k] * W1[(size_t)k * KMID + j];
            u[j] = acc;
        }
        __syncthreads();
        float s = 0.f, sq = 0.f;
        for (int j = tid; j < KMID; j += 256) { float v = u[j]; s += v; sq += v * v; }
        for (int d = 16; d; d >>= 1) { s += __shfl_xor_sync(~0u, s, d); sq += __shfl_xor_sync(~0u, sq, d); }
        if ((tid & 31) == 0) { red[tid >> 5] = s; red[8 + (tid >> 5)] = sq; }
        __syncthreads();
        if (tid == 0) {
            float S = 0.f, SQ = 0.f;
            for (int i = 0; i < 8; i++) { S += red[i]; SQ += red[8 + i]; }
            red[16] = S; red[17] = SQ;
        }
        __syncthreads();
        float mean = red[16] * (1.f / KMID);
        float var  = red[17] * (1.f / KMID) - mean * mean;
        float inv  = rsqrtf(var + 1e-5f);
        for (int j = tid; j < KMID; j += 256)
            h[j] = fmaxf((u[j] - mean) * inv * g1[j] + be1[j], 0.f);
        __syncthreads();
        if (tid < MAXN) {
            float acc = b2[tid];
            for (int j = 0; j < KMID; j++) acc += h[j] * W2[j * MAXN + tid];
            lg[tid] = acc;
        }
        __syncthreads();
        if (tid == 0) {
            float best = -1e30f; int bi = 0;
            #pragma unroll
            for (int o = 0; o < MAXN; o++)
                if (lg[o] > best) { best = lg[o]; bi = o; }
            g_n[w] = bi;
        }
        __syncthreads();
    }
}

// ---------------- exclusive scan ----------------
__global__ void scan_kernel()
{
    __shared__ int warpsum[32];
    int t = threadIdx.x, l = t & 31, w = t >> 5;
    int base = t * 32;
    int loc[32];
    int s = 0;
    #pragma unroll
    for (int i = 0; i < 32; i++) { loc[i] = s; s += g_n[base + i]; }
    int inc = s;
    #pragma unroll
    for (int d = 1; d < 32; d <<= 1) { int v = __shfl_up_sync(~0u, inc, d); if (l >= d) inc += v; }
    if (l == 31) warpsum[w] = inc;
    __syncthreads();
    if (w == 0) {
        int v = warpsum[l];
        #pragma unroll
        for (int d = 1; d < 32; d <<= 1) { int u2 = __shfl_up_sync(~0u, v, d); if (l >= d) v += u2; }
        warpsum[l] = v;
    }
    __syncthreads();
    int wbase = (w > 0) ? warpsum[w - 1] : 0;
    int exc = wbase + inc - s;
    #pragma unroll
    for (int i = 0; i < 32; i++) g_off[base + i] = exc + loc[i];
    if (t == 1023) g_total = wbase + inc;
}

__global__ void tokmap_kernel()
{
    int b = blockIdx.x * 256 + threadIdx.x;
    if (b >= NB) return;
    int off = g_off[b], n = g_n[b];
    for (int j = 0; j < n; j++) { g_tok_b[off + j] = b; g_tok_k[off + j] = (unsigned char)j; }
}

// ---------------- gatherA: zp = z[b]*keys[k] -> fp16, PACKED 128-row slabs ----------------
__global__ void gatherA_kernel(const float* __restrict__ z)
{
    int idx = blockIdx.x * 256 + threadIdx.x;
    int T = g_total;
    int rp = (T + 127) & ~127;
    if (idx >= rp * 4) return;
    int row = idx >> 2, q = idx & 3;
    int rc = min(row, T - 1);
    int b  = g_tok_b[rc];
    int kk = g_tok_k[rc];
    const float* zr = z + (size_t)b * HID;
    const float* kr = g_keys + kk * HID;
    int rt = row >> 7, rl = row & 127;
    #pragma unroll
    for (int jj = 0; jj < 16; jj++) {
        int kg = q * 128 + jj * 8;
        float4 a0 = *(const float4*)(zr + kg),     a1 = *(const float4*)(zr + kg + 4);
        float4 k0 = *(const float4*)(kr + kg),     k1 = *(const float4*)(kr + kg + 4);
        uint4 hv;
        hv.x = pack_h2(a0.x * k0.x, a0.y * k0.y);
        hv.y = pack_h2(a0.z * k0.z, a0.w * k0.w);
        hv.z = pack_h2(a1.x * k1.x, a1.y * k1.y);
        hv.w = pack_h2(a1.z * k1.z, a1.w * k1.w);
        int c = kg >> 6, kl = kg & 63;
        size_t off = (((size_t)(rt * 8 + c) * 128 + rl) * 64 + kl) * 2;
        *(uint4*)((char*)g_Ah + off) = hv;
    }
}

// ---------------- FUSED decoder (round-13 proven, byte-identical) ----------------
__global__ void __launch_bounds__(256, 1)
hmma_fused(const float* __restrict__ b1, const float* __restrict__ b2, float* __restrict__ Cg)
{
    constexpr int NC1 = HID / 64;
    constexpr int NC2 = DMID / 64;
    constexpr int CB  = 128 * 144;
    constexpr int CBG = 128 * 128;
    constexpr int HB  = 6 * CB;
    constexpr int STG = 2 * CB;

    int Meff = g_total;
    int row0 = blockIdx.x * 128;
    if (row0 >= Meff) return;
    int rt = blockIdx.x;

    extern __shared__ char dyn[];
    const uint32_t dynb = smem_u32(dyn);
    const uint32_t hbuf = dynb;
    const uint32_t pipe = dynb + HB;

    int tid  = threadIdx.x;
    int wid  = tid >> 5;
    int lane = tid & 31;
    int warp_m = wid & 3;
    int warp_n = wid >> 2;

    uint32_t a_off = (uint32_t)(warp_m * 32 + (lane & 15)) * 144 + ((lane >> 4) << 3) * 2;
    uint32_t b_off = (uint32_t)(warp_n * 64 + (lane & 7) + ((lane >> 4) << 3)) * 144
                   + (((lane >> 3) & 1) << 3) * 2;

    int rl_base = warp_m * 32 + (lane >> 2);
    int cl_base = warp_n * 64 + (lane & 3) * 2;

    const char* Ahg = (const char*)g_Ah;
    const char* B1g = (const char*)g_Bh;
    const char* B2g = (const char*)g_Bh + (size_t)B2_OFF * 2;

    auto cpA = [&](int c, int st) {
        uint32_t dh = pipe + st * STG;
        const char* sh = Ahg + (size_t)(rt * NC1 + c) * CBG;
        #pragma unroll
        for (int it = 0; it < 4; it++) {
            int tt = tid + 256 * it;
            int row = tt >> 3, sg = tt & 7;
            asm volatile("cp.async.cg.shared.global [%0], [%1], 16;"
                :: "r"(dh + row * 144 + sg * 16), "l"(sh + row * 128 + sg * 16));
        }
    };
    auto cpBto = [&](uint32_t dh, const char* Bg, int NT, int n0, int c) {
        const char* sh = Bg + ((size_t)c * NT + n0) * 144;
        #pragma unroll
        for (int it = 0; it < 5; it++) {
            int tt = tid + 256 * it;
            if (tt < 128 * 9) {
                int row = tt / 9, sg = tt - row * 9;
                uint32_t o = row * 144 + sg * 16;
                asm volatile("cp.async.cg.shared.global [%0], [%1], 16;" :: "r"(dh + o), "l"(sh + o));
            }
        }
    };

    float acc[2][8][4];

    for (int nt = 0; nt < 3; nt++) {
        int n0 = nt * 128;
        #pragma unroll
        for (int mi = 0; mi < 2; mi++)
            #pragma unroll
            for (int fj = 0; fj < 8; fj++)
                #pragma unroll
                for (int q = 0; q < 4; q++) acc[mi][fj][q] = 0.f;

        cpA(0, 0); cpBto(pipe + 0 * STG + CB, B1g, DMID, n0, 0);
        asm volatile("cp.async.commit_group;");
        cpA(1, 1); cpBto(pipe + 1 * STG + CB, B1g, DMID, n0, 1);
        asm volatile("cp.async.commit_group;");
        asm volatile("cp.async.wait_group 1;");
        __syncthreads();

        for (int c = 0; c < NC1; c++) {
            int st = c % 3;
            if (c + 2 < NC1) {
                int st2 = (c + 2) % 3;
                cpA(c + 2, st2); cpBto(pipe + st2 * STG + CB, B1g, DMID, n0, c + 2);
                asm volatile("cp.async.commit_group;");
            }
            uint32_t Ab = pipe + st * STG + a_off;
            uint32_t Bb = pipe + st * STG + CB + b_off;
            #pragma unroll
            for (int k16 = 0; k16 < 4; k16++) {
                uint32_t kb = (uint32_t)k16 * 32;
                uint32_t af[2][4];
                #pragma unroll
                for (int mi = 0; mi < 2; mi++) {
                    asm volatile("ldmatrix.sync.aligned.m8n8.x4.shared.b16 {%0,%1,%2,%3}, [%4];"
                        : "=r"(af[mi][0]), "=r"(af[mi][1]), "=r"(af[mi][2]), "=r"(af[mi][3])
                        : "r"(Ab + mi * 2304 + kb));
                }
                uint32_t bf[4][4];
                #pragma unroll
                for (int gj = 0; gj < 4; gj++) {
                    asm volatile("ldmatrix.sync.aligned.m8n8.x4.shared.b16 {%0,%1,%2,%3}, [%4];"
                        : "=r"(bf[gj][0]), "=r"(bf[gj][1]), "=r"(bf[gj][2]), "=r"(bf[gj][3])
                        : "r"(Bb + gj * 2304 + kb));
                }
                #pragma unroll
                for (int mi = 0; mi < 2; mi++)
                    #pragma unroll
                    for (int gj = 0; gj < 4; gj++)
                        #pragma unroll
                        for (int h = 0; h < 2; h++) {
                            int fj = gj * 2 + h;
                            asm volatile(
                                "mma.sync.aligned.m16n8k16.row.col.f32.f16.f16.f32 "
                                "{%0,%1,%2,%3},{%4,%5,%6,%7},{%8,%9},{%0,%1,%2,%3};"
                                : "+f"(acc[mi][fj][0]), "+f"(acc[mi][fj][1]),
                                  "+f"(acc[mi][fj][2]), "+f"(acc[mi][fj][3])
                                : "r"(af[mi][0]), "r"(af[mi][1]), "r"(af[mi][2]), "r"(af[mi][3]),
                                  "r"(bf[gj][h * 2]), "r"(bf[gj][h * 2 + 1]));
                        }
            }
            if (c + 1 < NC1) {
                if (c + 2 < NC1) { asm volatile("cp.async.wait_group 1;"); }
                else             { asm volatile("cp.async.wait_group 0;"); }
                __syncthreads();
            }
        }

        #pragma unroll
        for (int mi = 0; mi < 2; mi++) {
            #pragma unroll
            for (int fj = 0; fj < 8; fj++) {
                int colg = n0 + cl_base + fj * 8;
                int hc = colg >> 6, kl = colg & 63;
                float2 bv = *(const float2*)(b1 + colg);
                #pragma unroll
                for (int h2 = 0; h2 < 2; h2++) {
                    int row_l = rl_base + mi * 16 + h2 * 8;
                    float v0 = fmaxf(acc[mi][fj][h2 * 2 + 0] + bv.x, 0.f);
                    float v1 = fmaxf(acc[mi][fj][h2 * 2 + 1] + bv.y, 0.f);
                    *(uint32_t*)(dyn + (hc * 128 + row_l) * 144 + kl * 2) = pack_h2(v0, v1);
                }
            }
        }
        __syncthreads();
    }

    for (int nt2 = 0; nt2 < 2; nt2++) {
        int n0 = nt2 * 128;
        if (nt2 == 1) __syncthreads();
        #pragma unroll
        for (int mi = 0; mi < 2; mi++)
            #pragma unroll
            for (int fj = 0; fj < 8; fj++)
                #pragma unroll
                for (int q = 0; q < 4; q++) acc[mi][fj][q] = 0.f;

        #pragma unroll
        for (int c = 0; c < NC2; c++)
            cpBto(pipe + c * CB, B2g, DIM, n0, c);
        asm volatile("cp.async.commit_group;");
        asm volatile("cp.async.wait_group 0;");
        __syncthreads();

        for (int c = 0; c < NC2; c++) {
            uint32_t Ab = hbuf + c * CB + a_off;
            uint32_t Bb = pipe + c * CB + b_off;
            #pragma unroll
            for (int k16 = 0; k16 < 4; k16++) {
                uint32_t kb = (uint32_t)k16 * 32;
                uint32_t af[2][4];
                #pragma unroll
                for (int mi = 0; mi < 2; mi++) {
                    asm volatile("ldmatrix.sync.aligned.m8n8.x4.shared.b16 {%0,%1,%2,%3}, [%4];"
                        : "=r"(af[mi][0]), "=r"(af[mi][1]), "=r"(af[mi][2]), "=r"(af[mi][3])
                        : "r"(Ab + mi * 2304 + kb));
                }
                uint32_t bf[4][4];
                #pragma unroll
                for (int gj = 0; gj < 4; gj++) {
                    asm volatile("ldmatrix.sync.aligned.m8n8.x4.shared.b16 {%0,%1,%2,%3}, [%4];"
                        : "=r"(bf[gj][0]), "=r"(bf[gj][1]), "=r"(bf[gj][2]), "=r"(bf[gj][3])
                        : "r"(Bb + gj * 2304 + kb));
                }
                #pragma unroll
                for (int mi = 0; mi < 2; mi++)
                    #pragma unroll
                    for (int gj = 0; gj < 4; gj++)
                        #pragma unroll
                        for (int h = 0; h < 2; h++) {
                            int fj = gj * 2 + h;
                            asm volatile(
                                "mma.sync.aligned.m16n8k16.row.col.f32.f16.f16.f32 "
                                "{%0,%1,%2,%3},{%4,%5,%6,%7},{%8,%9},{%0,%1,%2,%3};"
                                : "+f"(acc[mi][fj][0]), "+f"(acc[mi][fj][1]),
                                  "+f"(acc[mi][fj][2]), "+f"(acc[mi][fj][3])
                                : "r"(af[mi][0]), "r"(af[mi][1]), "r"(af[mi][2]), "r"(af[mi][3]),
                                  "r"(bf[gj][h * 2]), "r"(bf[gj][h * 2 + 1]));
                        }
            }
        }

        #pragma unroll
        for (int mi = 0; mi < 2; mi++) {
            int r0 = row0 + rl_base + mi * 16;
            #pragma unroll
            for (int fj = 0; fj < 8; fj++) {
                int col = n0 + cl_base + fj * 8;
                float2 bv = *(const float2*)(b2 + col);
                float v0 = acc[mi][fj][0] + bv.x;
                float v1 = acc[mi][fj][1] + bv.y;
                float v2 = acc[mi][fj][2] + bv.x;
                float v3 = acc[mi][fj][3] + bv.y;
                if (r0 < Meff)     *(float2*)(Cg + (size_t)r0 * DIM + col)       = make_float2(v0, v1);
                if (r0 + 8 < Meff) *(float2*)(Cg + (size_t)(r0 + 8) * DIM + col) = make_float2(v2, v3);
            }
        }
    }
}

__global__ void batchout_kernel(float* __restrict__ out, long long out_size)
{
    int t = blockIdx.x * 256 + threadIdx.x;
    int total = g_total;
    if ((long long)total * 257 > out_size) return;
    if (t < total) out[(long long)total * 256 + t] = (float)g_tok_b[t];
}

// ---------------- launch ----------------
extern "C" void kernel_launch(void* const* d_in, const int* in_sizes, int n_in,
                              void* d_out, int out_size)
{
    const float* z     = (const float*)d_in[0];
    const float* kW1   = (const float*)d_in[1];
    const float* kb1   = (const float*)d_in[2];
    const float* kg1   = (const float*)d_in[3];
    const float* kbe1  = (const float*)d_in[4];
    const float* kW2   = (const float*)d_in[5];
    const float* kb2   = (const float*)d_in[6];
    const float* dW1   = (const float*)d_in[7];
    const float* db1   = (const float*)d_in[8];
    const float* dW2   = (const float*)d_in[9];
    const float* db2   = (const float*)d_in[10];
    const float* spW1  = (const float*)d_in[11];
    const float* spb1  = (const float*)d_in[12];
    const float* spg1  = (const float*)d_in[13];
    const float* spbe1 = (const float*)d_in[14];
    const float* spW2  = (const float*)d_in[15];
    const float* spb2  = (const float*)d_in[16];
    float* out = (float*)d_out;

    constexpr int SMEM_FUSED = 6 * 128 * 144 + 3 * 2 * 128 * 144;   // 221184
    constexpr int SMEM_SP    = 3 * 2 * 128 * 144;                   // 110592
    cudaFuncSetAttribute(hmma_fused, cudaFuncAttributeMaxDynamicSharedMemorySize, SMEM_FUSED);
    cudaFuncSetAttribute(sp_hmma,    cudaFuncAttributeMaxDynamicSharedMemorySize, SMEM_SP);

    // weight prep (fp16)
    prep_kernel<B1_OFF><<<(DMID * (HID / 8) + 255) / 256, 256>>>(dW1, HID, DMID);
    prep_kernel<B2_OFF><<<(DIM * (DMID / 8) + 255) / 256, 256>>>(dW2, DMID, DIM);
    prep_sp_kernel<<<(NSPPAD * (HID / 8) + 255) / 256, 256>>>(spW1);

    // z -> fp16 slabs (+ flag counter reset)
    zprep_kernel<<<NB * 4 / 256, 256>>>(z);

    // 17 key rows
    keys_kernel<<<dim3(17, 8), 256>>>(kW1, kb1, kg1, kbe1, kW2, kb2);

    // sp GEMM on tensor cores: U = z16 @ W1_16 + b
    sp_hmma<<<dim3(3, NB / 128), 256, SMEM_SP>>>(spb1);

    // size-pred with margin gate -> g_n (+ flagged rows)
    sizepred_kernel<<<NB / 8, 256>>>(spW2, spb2, spg1, spbe1);

    // fp32 exact re-decision for flagged rows
    sp_fallback<<<1024, 256>>>(z, spW1, spb1, spg1, spbe1, spW2, spb2);

    // offsets -> token map
    scan_kernel<<<1, 1024>>>();
    tokmap_kernel<<<NB / 256, 256>>>();

    // pre-round A = z[b]*keys[k] (fp16)
    gatherA_kernel<<<TMAX * 4 / 256, 256>>>(z);

    // fused decoder: both layers, one CTA per 128-row tile
    hmma_fused<<<TMAX / 128, 256, SMEM_FUSED>>>(db1, db2, out);

    // optional batch ids
    batchout_kernel<<<TMAX / 256, 256>>>(out, (long long)out_size);
}